// round 8
// baseline (speedup 1.0000x reference)
#include <cuda_runtime.h>
#include <math.h>

#define Hh   16
#define DU   64
#define DP   32
#define Dd   96
#define Bn   16
#define TCACHE 4095
#define TT   4096
#define WIN  512
#define Fdim 1536

#define TILE_R 32                 // rows per tile
#define NTILES 16                 // WIN / TILE_R
#define NBUF   4                  // pipeline depth
#define TILE_F (TILE_R * Dd)      // floats per tile (3072 = 12KB)

static __device__ __forceinline__ void cp_async16(float* smem_dst, const float* gmem_src) {
    unsigned saddr = (unsigned)__cvta_generic_to_shared(smem_dst);
    asm volatile("cp.async.cg.shared.global [%0], [%1], 16;" :: "r"(saddr), "l"(gmem_src));
}
static __device__ __forceinline__ void cp_commit() { asm volatile("cp.async.commit_group;"); }
static __device__ __forceinline__ void cp_wait2()  { asm volatile("cp.async.wait_group 2;" ::: "memory"); }

__global__ __launch_bounds__(256, 2)
void bichan_attn_kernel(const float* __restrict__ content,
                        const float* __restrict__ cache,
                        const float* __restrict__ Wq_u, const float* __restrict__ bq_u,
                        const float* __restrict__ Wk_u, const float* __restrict__ bk_u,
                        const float* __restrict__ Wv_u, const float* __restrict__ bv_u,
                        const float* __restrict__ Wq_p, const float* __restrict__ bq_p,
                        const float* __restrict__ Wk_p, const float* __restrict__ bk_p,
                        const float* __restrict__ Wv_p, const float* __restrict__ bv_p,
                        const float* __restrict__ pos_param_p,
                        float* __restrict__ out)
{
    extern __shared__ __align__(16) float s_tiles[];   // NBUF * TILE_F floats

    const int h    = blockIdx.x;
    const int b    = blockIdx.y;
    const int tid  = threadIdx.x;
    const int lane = tid & 31;
    const int w    = tid >> 5;
    const int qq   = lane >> 3;   // quarter: position within the warp's 4-row group
    const int s    = lane & 7;    // sublane: 12 dims of the row
    const int s4   = s * 4;

    __shared__ float s_u[Dd];
    __shared__ float s_q[Dd];
    __shared__ alignas(16) float s_qt[Dd];
    __shared__ float s_bias[WIN];
    __shared__ float s_const;
    __shared__ float s_gm[32], s_gl[32];
    __shared__ alignas(16) float s_gacc[32][Dd];
    __shared__ alignas(16) float s_cbar[Dd];

    const float  pp    = *pos_param_p;
    const float* crow  = content + (size_t)b * Fdim + h * Dd;
    const float* cbase = cache   + ((size_t)b * TCACHE) * Fdim + h * Dd;

    // ---- async tile producer: 768 float4 per tile, 3 per thread ----
    auto load_tile = [&](int t) {
        float* dst = s_tiles + (size_t)(t & (NBUF - 1)) * TILE_F;
        int idx = tid;
        #pragma unroll
        for (int k = 0; k < 3; k++, idx += 256) {
            int r = idx / 24;            // row within tile (24 float4 per row)
            int c = idx % 24;
            int j = (TT - WIN) + t * TILE_R + r;
            const float* src = (j < TCACHE) ? (cbase + (size_t)j * Fdim + c * 4)
                                            : (crow + c * 4);
            cp_async16(dst + r * Dd + c * 4, src);
        }
    };

    // Kick off the pipeline immediately — overlaps with projection setup below.
    load_tile(0); cp_commit();
    load_tile(1); cp_commit();
    load_tile(2); cp_commit();

    if (tid < Dd) s_u[tid] = crow[tid];

    // time_mask collapses to a uniform shift (softmax-invariant) -> ignored.
    for (int p = tid; p < WIN; p += 256) {
        int n = (WIN - 1) - p;
        float bucket;
        if (n < 16) bucket = (float)n;
        else {
            int bb = 16 + (int)((log((double)n * (1.0 / 16.0)) / log(8.0)) * 16.0);
            bucket = (float)(bb < 31 ? bb : 31);
        }
        s_bias[p] = -pp * bucket;
    }
    __syncthreads();

    // ---- q projection ----
    if (tid < DU) {
        const float* Wc = Wq_u + ((size_t)h * DU) * DU + tid;
        float acc = bq_u[h * DU + tid];
        #pragma unroll 8
        for (int d = 0; d < DU; d++) acc = fmaf(s_u[d], Wc[d * DU], acc);
        s_q[tid] = acc;
    } else if (tid < Dd) {
        int e = tid - DU;
        const float* Wc = Wq_p + ((size_t)h * DP) * DP + e;
        float acc = bq_p[h * DP + e];
        #pragma unroll 8
        for (int d = 0; d < DP; d++) acc = fmaf(s_u[DU + d], Wc[d * DP], acc);
        s_q[tid] = acc;
    }
    __syncthreads();

    // ---- fold K projection: qt = (Wk q)/sqrt(D), const = (q.bk)/sqrt(D) ----
    const float inv = 1.0f / sqrtf((float)Dd);
    if (tid < DU) {
        const float4* Wr = (const float4*)(Wk_u + ((size_t)h * DU + tid) * DU);
        float acc = 0.f;
        #pragma unroll
        for (int e4 = 0; e4 < DU / 4; e4++) {
            float4 wv = Wr[e4];
            acc += wv.x * s_q[e4*4] + wv.y * s_q[e4*4+1] + wv.z * s_q[e4*4+2] + wv.w * s_q[e4*4+3];
        }
        s_qt[tid] = acc * inv;
    } else if (tid < Dd) {
        int d = tid - DU;
        const float4* Wr = (const float4*)(Wk_p + ((size_t)h * DP + d) * DP);
        float acc = 0.f;
        #pragma unroll
        for (int e4 = 0; e4 < DP / 4; e4++) {
            float4 wv = Wr[e4];
            acc += wv.x * s_q[DU+e4*4] + wv.y * s_q[DU+e4*4+1] + wv.z * s_q[DU+e4*4+2] + wv.w * s_q[DU+e4*4+3];
        }
        s_qt[tid] = acc * inv;
    } else if (tid == Dd) {
        float acc = 0.f;
        for (int e = 0; e < DU; e++) acc = fmaf(s_q[e],      bk_u[h * DU + e], acc);
        for (int e = 0; e < DP; e++) acc = fmaf(s_q[DU + e], bk_p[h * DP + e], acc);
        s_const = acc * inv;
    }
    __syncthreads();

    // ---- main pass: smem-pipelined online softmax ----
    // Tile t rows 0..31; warp w owns rows w*4 + qq (one per quarter).
    const float4* q4 = (const float4*)s_qt;
    const float4  qtA = q4[s], qtB = q4[8 + s], qtC = q4[16 + s];
    const float   sc  = s_const;
    const int     r   = (w << 2) | qq;

    float m = -INFINITY, l = 0.f;
    float4 aA = {0,0,0,0}, aB = {0,0,0,0}, aC = {0,0,0,0};

    for (int t = 0; t < NTILES; t++) {
        cp_wait2();            // tile t resident (this thread's copies)
        __syncthreads();       // everyone's copies visible; old buffer free

        if (t + NBUF - 1 < NTILES) load_tile(t + NBUF - 1);
        cp_commit();           // always commit (possibly empty) -> wait count stays fixed

        const float* B = s_tiles + (size_t)(t & (NBUF - 1)) * TILE_F + r * Dd;
        float4 va = *(const float4*)(B + s4);
        float4 vb = *(const float4*)(B + 32 + s4);
        float4 vc = *(const float4*)(B + 64 + s4);

        float x;
        x = va.x * qtA.x;          x = fmaf(va.y, qtA.y, x);
        x = fmaf(va.z, qtA.z, x);  x = fmaf(va.w, qtA.w, x);
        x = fmaf(vb.x, qtB.x, x);  x = fmaf(vb.y, qtB.y, x);
        x = fmaf(vb.z, qtB.z, x);  x = fmaf(vb.w, qtB.w, x);
        x = fmaf(vc.x, qtC.x, x);  x = fmaf(vc.y, qtC.y, x);
        x = fmaf(vc.z, qtC.z, x);  x = fmaf(vc.w, qtC.w, x);
        x += __shfl_xor_sync(0xffffffffu, x, 1);
        x += __shfl_xor_sync(0xffffffffu, x, 2);
        x += __shfl_xor_sync(0xffffffffu, x, 4);

        float score = x + sc + s_bias[t * TILE_R + r];
        float mnew  = fmaxf(m, score);
        float corr  = __expf(m - mnew);
        float e     = __expf(score - mnew);
        l = fmaf(l, corr, e);
        aA.x = fmaf(aA.x, corr, e * va.x); aA.y = fmaf(aA.y, corr, e * va.y);
        aA.z = fmaf(aA.z, corr, e * va.z); aA.w = fmaf(aA.w, corr, e * va.w);
        aB.x = fmaf(aB.x, corr, e * vb.x); aB.y = fmaf(aB.y, corr, e * vb.y);
        aB.z = fmaf(aB.z, corr, e * vb.z); aB.w = fmaf(aB.w, corr, e * vb.w);
        aC.x = fmaf(aC.x, corr, e * vc.x); aC.y = fmaf(aC.y, corr, e * vc.y);
        aC.z = fmaf(aC.z, corr, e * vc.z); aC.w = fmaf(aC.w, corr, e * vc.w);
        m = mnew;
    }

    // ---- write 32 partial softmax groups (warp x quarter) ----
    const int g = (w << 2) | qq;
    if (s == 0) { s_gm[g] = m; s_gl[g] = l; }
    *(float4*)&s_gacc[g][s4]      = aA;
    *(float4*)&s_gacc[g][32 + s4] = aB;
    *(float4*)&s_gacc[g][64 + s4] = aC;
    __syncthreads();

    // ---- combine 32 groups ----
    if (tid < Dd) {
        float M = s_gm[0];
        #pragma unroll
        for (int gg = 1; gg < 32; gg++) M = fmaxf(M, s_gm[gg]);
        float L = 0.f, a = 0.f;
        #pragma unroll
        for (int gg = 0; gg < 32; gg++) {
            float scl = __expf(s_gm[gg] - M);
            L = fmaf(s_gl[gg], scl, L);
            a = fmaf(s_gacc[gg][tid], scl, a);
        }
        s_cbar[tid] = a / L;
    }
    __syncthreads();

    // ---- output projection through Wv + residual ----
    if (tid < DU) {
        const float* Wc = Wv_u + ((size_t)h * DU) * DU + tid;
        float acc = bv_u[h * DU + tid];
        #pragma unroll 8
        for (int d = 0; d < DU; d++) acc = fmaf(s_cbar[d], Wc[d * DU], acc);
        out[(size_t)b * Fdim + h * Dd + tid] = acc + s_u[tid];
    } else if (tid < Dd) {
        int e = tid - DU;
        const float* Wc = Wv_p + ((size_t)h * DP) * DP + e;
        float acc = bv_p[h * DP + e];
        #pragma unroll 8
        for (int d = 0; d < DP; d++) acc = fmaf(s_cbar[DU + d], Wc[d * DP], acc);
        out[(size_t)b * Fdim + h * Dd + tid] = acc + s_u[tid];
    }
}

extern "C" void kernel_launch(void* const* d_in, const int* in_sizes, int n_in,
                              void* d_out, int out_size)
{
    const float* content = (const float*)d_in[1];
    const float* cache   = (const float*)d_in[3];
    const float* Wq_u    = (const float*)d_in[5];
    const float* bq_u    = (const float*)d_in[6];
    const float* Wk_u    = (const float*)d_in[7];
    const float* bk_u    = (const float*)d_in[8];
    const float* Wv_u    = (const float*)d_in[9];
    const float* bv_u    = (const float*)d_in[10];
    const float* Wq_p    = (const float*)d_in[11];
    const float* bq_p    = (const float*)d_in[12];
    const float* Wk_p    = (const float*)d_in[13];
    const float* bk_p    = (const float*)d_in[14];
    const float* Wv_p    = (const float*)d_in[15];
    const float* bv_p    = (const float*)d_in[16];
    const float* pos_p   = (const float*)d_in[17];
    float* out = (float*)d_out;

    const int dyn_smem = NBUF * TILE_F * (int)sizeof(float);   // 48 KB
    cudaFuncSetAttribute(bichan_attn_kernel,
                         cudaFuncAttributeMaxDynamicSharedMemorySize, dyn_smem);

    dim3 grid(Hh, Bn);
    bichan_attn_kernel<<<grid, 256, dyn_smem>>>(content, cache,
                                                Wq_u, bq_u, Wk_u, bk_u, Wv_u, bv_u,
                                                Wq_p, bq_p, Wk_p, bk_p, Wv_p, bv_p,
                                                pos_p, out);
}